// round 4
// baseline (speedup 1.0000x reference)
#include <cuda_runtime.h>
#include <cstddef>

#define BATCH 4
#define CIN   48
#define C6    288
#define C2    96
#define HH    256
#define WW    256
#define ST    68   // padded smem row stride (floats) for K2 tiles

// 302 MB scratch for qkv = dw3x3(conv1x1(x)); q=[0,96), k=[96,192), v=[192,288)
__device__ float g_qkv[(size_t)BATCH * C6 * HH * WW];

// ---------------------------------------------------------------------------
// K1: fused 1x1 conv (48->288, bias) + depthwise 3x3 SAME (bias) -> g_qkv
// grid (16,16,B), block 352. 4 output channels per iteration.
// ---------------------------------------------------------------------------
__global__ void __launch_bounds__(352, 2)
fsas_k1(const float* __restrict__ x,
        const float* __restrict__ w1,
        const float* __restrict__ b1,
        const float* __restrict__ wdw,
        const float* __restrict__ bdw) {
    extern __shared__ float sm1[];
    float* w1s  = sm1;               // C6*CIN = 13824
    float* wdws = w1s + C6 * CIN;    // C6*9   = 2592
    float* hid  = wdws + C6 * 9;     // 4*324  = 1296

    const int tid = threadIdx.x;
    const int b  = blockIdx.z;
    const int h0 = blockIdx.y * 16;
    const int w0 = blockIdx.x * 16;

    for (int i = tid; i < C6 * CIN; i += blockDim.x) w1s[i] = w1[i];
    for (int i = tid; i < C6 * 9;   i += blockDim.x) wdws[i] = wdw[i];

    // each thread owns one halo pixel (18x18 = 324) and register-caches x[ch]
    const int s  = tid;
    const int ty = s / 18, tx = s % 18;
    const int hh = h0 - 1 + ty;
    const int ww = w0 - 1 + tx;
    const bool inimg = (s < 324) && hh >= 0 && hh < HH && ww >= 0 && ww < WW;

    float xr[CIN];
    if (inimg) {
        const float* xp = x + ((size_t)b * CIN) * HH * WW + (size_t)hh * WW + ww;
        #pragma unroll
        for (int c = 0; c < CIN; c++) xr[c] = xp[(size_t)c * HH * WW];
    } else {
        #pragma unroll
        for (int c = 0; c < CIN; c++) xr[c] = 0.0f;
    }

    __syncthreads();

    for (int o = 0; o < C6; o += 4) {
        if (s < 324) {
            float a0[4] = {0.f, 0.f, 0.f, 0.f};
            float a1[4] = {0.f, 0.f, 0.f, 0.f};
            #pragma unroll
            for (int c = 0; c < CIN; c += 2) {
                const float x0 = xr[c], x1 = xr[c + 1];
                #pragma unroll
                for (int q = 0; q < 4; q++) {
                    const float* wr = &w1s[(o + q) * CIN + c];
                    a0[q] += wr[0] * x0;
                    a1[q] += wr[1] * x1;
                }
            }
            #pragma unroll
            for (int q = 0; q < 4; q++)
                hid[q * 324 + s] = inimg ? (a0[q] + a1[q] + b1[o + q]) : 0.0f;
        }
        __syncthreads();
        // depthwise 3x3 over 4 channels x 256 pixels, all 352 threads
        for (int u = tid; u < 1024; u += 352) {
            const int q   = u >> 8;
            const int pix = u & 255;
            const int py  = pix >> 4, px = pix & 15;
            const float* wd = &wdws[(o + q) * 9];
            const float* hb = &hid[q * 324];
            float acc = bdw[o + q];
            #pragma unroll
            for (int dy = 0; dy < 3; dy++)
                #pragma unroll
                for (int dx = 0; dx < 3; dx++)
                    acc += wd[dy * 3 + dx] * hb[(py + dy) * 18 + (px + dx)];
            g_qkv[(((size_t)b * C6 + o + q) * HH + (h0 + py)) * WW + (w0 + px)] = acc;
        }
        __syncthreads();
    }
}

// ---------------------------------------------------------------------------
// K2: per 64-col segment of one row: circular conv (8x8 on flat 64 chunk),
// channel LayerNorm (96), v*normed, 1x1 conv 96->48, write output.
// grid (4, 256, B), block 256, 2 CTAs/SM. Padded stride 68 => conflict-free.
// ---------------------------------------------------------------------------
__global__ void __launch_bounds__(256, 2)
fsas_k2(const float* __restrict__ gamma,
        const float* __restrict__ beta,
        const float* __restrict__ wout,
        const float* __restrict__ bout,
        float* __restrict__ out) {
    extern __shared__ float sm2[];
    float* qs   = sm2;                 // C2*ST  (reused for nv)
    float* ks   = qs + C2 * ST;        // C2*ST  (reused for circ-conv output)
    float* vs   = ks + C2 * ST;        // C2*ST
    float* wos  = vs + C2 * ST;        // CIN*C2
    float* mus  = wos + CIN * C2;      // 64
    float* rss  = mus + 64;            // 64
    float* gms  = rss + 64;            // C2
    float* bts  = gms + C2;            // C2

    const int tid = threadIdx.x;
    const int b  = blockIdx.z;
    const int h  = blockIdx.y;
    const int w0 = blockIdx.x * 64;

    const size_t plane = (size_t)HH * WW;
    const size_t base  = (((size_t)b * C6) * HH + h) * WW + w0;

    // ---- load q,k,v tiles (float4) + weights -----------------------------
    for (int i4 = tid; i4 < C2 * 16; i4 += 256) {
        const int ch = i4 >> 4, z4 = (i4 & 15) << 2;
        const size_t off = base + (size_t)ch * plane + z4;
        *(float4*)&qs[ch * ST + z4] = *(const float4*)&g_qkv[off];
        *(float4*)&ks[ch * ST + z4] = *(const float4*)&g_qkv[off + (size_t)C2 * plane];
        *(float4*)&vs[ch * ST + z4] = *(const float4*)&g_qkv[off + (size_t)(2 * C2) * plane];
    }
    for (int i = tid; i < CIN * C2; i += 256) wos[i] = wout[i];
    if (tid < C2) { gms[tid] = gamma[tid]; bts[tid] = beta[tid]; }
    __syncthreads();

    // ---- 2D circular conv: thread (ch, 4 consecutive m rows) -------------
    float acc[4][8];
    const int cc = (tid < 96) ? tid : tid - 96;   // channel
    const int m0 = (tid < 96) ? 0 : 4;            // first m row
    if (tid < 192) {
        #pragma unroll
        for (int j = 0; j < 4; j++)
            #pragma unroll
            for (int n = 0; n < 8; n++) acc[j][n] = 0.0f;
        const float* qb = &qs[cc * ST];
        const float* kb = &ks[cc * ST];
        #pragma unroll
        for (int p = 0; p < 8; p++) {
            const float4 qa = *(const float4*)&qb[p * 8];
            const float4 qc = *(const float4*)&qb[p * 8 + 4];
            const float qv[8] = {qa.x,qa.y,qa.z,qa.w,qc.x,qc.y,qc.z,qc.w};
            #pragma unroll
            for (int j = 0; j < 4; j++) {
                const int kr = ((m0 + j - p) & 7) * 8;
                const float4 ka = *(const float4*)&kb[kr];
                const float4 kc = *(const float4*)&kb[kr + 4];
                const float kv[8] = {ka.x,ka.y,ka.z,ka.w,kc.x,kc.y,kc.z,kc.w};
                #pragma unroll
                for (int r = 0; r < 8; r++) {
                    #pragma unroll
                    for (int n = 0; n < 8; n++)
                        acc[j][n] += qv[r] * kv[(n - r) & 7];
                }
            }
        }
    }
    __syncthreads();           // all reads of qs/ks done
    if (tid < 192) {
        #pragma unroll
        for (int j = 0; j < 4; j++) {
            *(float4*)&ks[cc * ST + (m0 + j) * 8]     = *(float4*)&acc[j][0];
            *(float4*)&ks[cc * ST + (m0 + j) * 8 + 4] = *(float4*)&acc[j][4];
        }
    }
    __syncthreads();

    // ---- LayerNorm stats over 96 channels per pixel ----------------------
    if (tid < 64) {
        float sum = 0.f, sq = 0.f;
        #pragma unroll
        for (int ch = 0; ch < C2; ch++) {
            const float v = ks[ch * ST + tid];
            sum += v; sq += v * v;
        }
        const float mu  = sum * (1.0f / C2);
        const float var = sq * (1.0f / C2) - mu * mu;
        mus[tid] = mu;
        rss[tid] = rsqrtf(var + 1e-5f);
    }
    __syncthreads();

    // ---- nv = v * normed, stored [ch][z] stride ST into qs ---------------
    for (int i = tid; i < C2 * 64; i += 256) {
        const int ch = i >> 6, z = i & 63;
        const float o_ = ks[ch * ST + z];
        const float nrm = (o_ - mus[z]) * rss[z] * gms[ch] + bts[ch];
        qs[ch * ST + z] = vs[ch * ST + z] * nrm;
    }
    __syncthreads();

    // ---- final 1x1 conv 96->48: thread = (q4, z), 12 co each -------------
    {
        const int q4 = tid >> 6;           // 0..3
        const int z  = tid & 63;
        float facc[12];
        #pragma unroll
        for (int c = 0; c < 12; c++) facc[c] = 0.f;
        #pragma unroll
        for (int cb = 0; cb < C2; cb += 4) {
            const float nv0 = qs[(cb + 0) * ST + z];
            const float nv1 = qs[(cb + 1) * ST + z];
            const float nv2 = qs[(cb + 2) * ST + z];
            const float nv3 = qs[(cb + 3) * ST + z];
            #pragma unroll
            for (int c = 0; c < 12; c++) {
                const float4 w4 = *(const float4*)&wos[(q4 * 12 + c) * C2 + cb];
                facc[c] += w4.x * nv0 + w4.y * nv1 + w4.z * nv2 + w4.w * nv3;
            }
        }
        const size_t obase = (((size_t)b * CIN + q4 * 12) * HH + h) * WW + w0 + z;
        #pragma unroll
        for (int c = 0; c < 12; c++)
            out[obase + (size_t)c * HH * WW] = facc[c] + bout[q4 * 12 + c];
    }
}

// ---------------------------------------------------------------------------
extern "C" void kernel_launch(void* const* d_in, const int* in_sizes, int n_in,
                              void* d_out, int out_size) {
    const float* x        = (const float*)d_in[0];
    const float* w_hidden = (const float*)d_in[1];
    const float* b_hidden = (const float*)d_in[2];
    const float* w_dw     = (const float*)d_in[3];
    const float* b_dw     = (const float*)d_in[4];
    const float* gamma    = (const float*)d_in[5];
    const float* beta     = (const float*)d_in[6];
    const float* w_out    = (const float*)d_in[7];
    const float* b_out    = (const float*)d_in[8];
    float* out = (float*)d_out;

    const int smem1 = (C6 * CIN + C6 * 9 + 4 * 324) * sizeof(float);
    const int smem2 = (3 * C2 * ST + CIN * C2 + 128 + 2 * C2) * sizeof(float);
    cudaFuncSetAttribute(fsas_k1, cudaFuncAttributeMaxDynamicSharedMemorySize, smem1);
    cudaFuncSetAttribute(fsas_k2, cudaFuncAttributeMaxDynamicSharedMemorySize, smem2);

    fsas_k1<<<dim3(16, 16, BATCH), 352, smem1>>>(x, w_hidden, b_hidden, w_dw, b_dw);
    fsas_k2<<<dim3(4, 256, BATCH), 256, smem2>>>(gamma, beta, w_out, b_out, out);
}